// round 15
// baseline (speedup 1.0000x reference)
#include <cuda_runtime.h>
#include <cstdint>

// trans_b: [32, 64, 256, 256] fp32 -> 2048 planes x 16384 float4
#define NPLANES     2048
#define PLANE_F4    16384
#define NBATCH      32
#define NSTAGES     16            // 2 batches per stage (33.6 MB, L2-resident)
#define POOL_PS     512           // pool quarter-plane blocks per stage
#define SCALE_PS    2048          // scale blocks per stage (1024 f4 each)
#define BLKS_PS     2560          // POOL_PS + SCALE_PS
#define QUARTER_F4  4096
#define SCALE_PB    1024          // scale blocks per batch
#define QUART_PB    256           // pool quarters per batch

__device__ float             g_partial[NPLANES * 4];  // per-quarter sums
__device__ float             g_scale[NPLANES];
__device__ unsigned          g_qdone[NBATCH];         // quarters done (self-resets)
__device__ volatile unsigned g_ready[NBATCH];         // reset by last scaler
__device__ unsigned          g_sdone[NBATCH];         // scalers done (self-resets)

// ---------------------------------------------------------------------------
// One launch, bids organized in 16 stages of [512 pool | 2048 scale] blocks.
// HW dispatches in bid order, so scale(s) runs right after pool(s): its data
// is still L2-resident -> second read becomes L2 hits instead of DRAM.
// Deadlock-free: every waiter's producers have strictly lower bids.
// Replay-safe: counters atomicSub-self-reset; ready[b] cleared by the last
// scale block of batch b (all waiters provably past the spin).
// ---------------------------------------------------------------------------
__global__ void __launch_bounds__(256) se_staged_kernel(
    const float* __restrict__ x, float* __restrict__ y,
    const float* __restrict__ w_down,  // [4, 64]
    const float* __restrict__ b_down,  // [4]
    const float* __restrict__ w_up,    // [64, 4]
    const float* __restrict__ b_up)    // [64]
{
    const int tid   = threadIdx.x;
    const int stage = blockIdx.x / BLKS_PS;
    const int r     = blockIdx.x % BLKS_PS;
    const float4* __restrict__ px = reinterpret_cast<const float4*>(x);
    float4*       __restrict__ py = reinterpret_cast<float4*>(y);

    if (r < POOL_PS) {
        // ============ POOL one quarter-plane (64 KB, 16 f4/thread) ========
        const int unit  = stage * POOL_PS + r;       // 0..8191 == plane*4+q
        const int plane = unit >> 2;
        const size_t base = ((size_t)plane << 14) + ((size_t)(unit & 3) << 12);

        float a0 = 0.0f, a1 = 0.0f;
        #pragma unroll
        for (int i = 0; i < 16; i += 2) {            // front-batched pairs
            float4 v = __ldcg(px + base + tid + (size_t)i * 256);
            float4 w = __ldcg(px + base + tid + (size_t)(i + 1) * 256);
            a0 += (v.x + v.y) + (v.z + v.w);
            a1 += (w.x + w.y) + (w.z + w.w);
        }
        float sum = a0 + a1;
        #pragma unroll
        for (int o = 16; o > 0; o >>= 1)
            sum += __shfl_xor_sync(0xFFFFFFFFu, sum, o);

        __shared__ float sred[8];
        __shared__ int   s_last;
        if ((tid & 31) == 0) sred[tid >> 5] = sum;
        __syncthreads();

        if (tid == 0) {
            float t = (sred[0] + sred[1]) + (sred[2] + sred[3])
                    + (sred[4] + sred[5]) + (sred[6] + sred[7]);
            __stcg(&g_partial[unit], t);
            __threadfence();                          // publish before counting
            unsigned old = atomicAdd(&g_qdone[plane >> 6], 1u);
            if (old == QUART_PB - 1u) {
                atomicSub(&g_qdone[plane >> 6], QUART_PB);   // replay-safe reset
                s_last = 1;
            } else s_last = 0;
        }
        __syncthreads();

        if (s_last) {
            // Batch complete: fixed-order reduction + MLP (deterministic).
            const int b = plane >> 6;
            __shared__ float pooled[64];
            __shared__ float hidden[4];

            if (tid == 0) __threadfence();            // acquire all partials
            __syncthreads();
            if (tid < 64) {
                const float* pp = g_partial + ((size_t)(b * 64 + tid) << 2);
                pooled[tid] = ((__ldcg(pp + 0) + __ldcg(pp + 1)) +
                               (__ldcg(pp + 2) + __ldcg(pp + 3))) * (1.0f / 65536.0f);
            }
            __syncthreads();
            if (tid < 4) {
                float h = b_down[tid];
                #pragma unroll 8
                for (int k = 0; k < 64; k++)
                    h = fmaf(pooled[k], __ldg(&w_down[tid * 64 + k]), h);
                hidden[tid] = fmaxf(h, 0.0f);
            }
            __syncthreads();
            if (tid < 64) {
                float s = b_up[tid];
                #pragma unroll
                for (int m = 0; m < 4; m++)
                    s = fmaf(hidden[m], __ldg(&w_up[tid * 4 + m]), s);
                __stcg(&g_scale[b * 64 + tid], 1.0f / (1.0f + expf(-s)));
            }
            __syncthreads();
            if (tid == 0) {
                __threadfence();                      // release g_scale[b]
                g_ready[b] = 1u;
            }
        }
    } else {
        // ============ SCALE one 16 KB chunk (ILP-4) =======================
        const unsigned schunk = (unsigned)stage * SCALE_PS + (unsigned)(r - POOL_PS);
        const unsigned b      = schunk >> 10;

        if (tid == 0) {
            while (g_ready[b] == 0u) __nanosleep(64); // one-shot read-only spin
            __threadfence();                          // acquire g_scale
        }
        __syncthreads();

        const size_t base = (size_t)schunk * 1024 + tid;
        const float s = __ldcg(&g_scale[base >> 14]); // uniform in block

        float4 v0 = __ldcs(px + base);                // L2 hit, evict after read
        float4 v1 = __ldcs(px + base + 256);
        float4 v2 = __ldcs(px + base + 512);
        float4 v3 = __ldcs(px + base + 768);

        v0.x *= s; v0.y *= s; v0.z *= s; v0.w *= s;
        v1.x *= s; v1.y *= s; v1.z *= s; v1.w *= s;
        v2.x *= s; v2.y *= s; v2.z *= s; v2.w *= s;
        v3.x *= s; v3.y *= s; v3.z *= s; v3.w *= s;

        __stcs(py + base,       v0);                  // streaming stores
        __stcs(py + base + 256, v1);
        __stcs(py + base + 512, v2);
        __stcs(py + base + 768, v3);

        __syncthreads();                              // whole block past spin
        if (tid == 0) {
            unsigned old = atomicAdd(&g_sdone[b], 1u);
            if (old == SCALE_PB - 1u) {               // last scaler of batch b
                g_ready[b] = 0u;                      // reset flag for replay
                atomicSub(&g_sdone[b], SCALE_PB);
            }
        }
    }
}

// ---------------------------------------------------------------------------
extern "C" void kernel_launch(void* const* d_in, const int* in_sizes, int n_in,
                              void* d_out, int out_size)
{
    const float* trans_b = (const float*)d_in[0];
    const float* w_down  = (const float*)d_in[1];
    const float* b_down  = (const float*)d_in[2];
    const float* w_up    = (const float*)d_in[3];
    const float* b_up    = (const float*)d_in[4];
    float* out = (float*)d_out;

    se_staged_kernel<<<NSTAGES * BLKS_PS, 256>>>(
        trans_b, out, w_down, b_down, w_up, b_up);
}